// round 5
// baseline (speedup 1.0000x reference)
#include <cuda_runtime.h>

// Problem constants
#define NB   4
#define NC   128
#define C8   16
#define HH   64
#define WW   64
#define HWSZ 4096   // 64*64

typedef unsigned long long ull;

// ---------------- scratch (static device globals; no runtime alloc) -------
__device__ float g_Qt [NB * C8 * HWSZ];     // [b][c8][p]
__device__ float g_Kt [NB * C8 * HWSZ];     // [b][c8][p]
__device__ float g_V  [NB * NC * HWSZ];     // [b][c][p]
__device__ float g_sel[NB * NC * HWSZ];     // [b][c][p]
__device__ float g_maxv[NB * HWSZ];
__device__ float g_m8 [8 * NB * HWSZ];      // per-q-partition max
__device__ int   g_i8 [8 * NB * HWSZ];      // per-q-partition argmax
__device__ float g_part[NB * NC * HWSZ];    // x-half conv partials
__device__ float g_Wt [2 * NC * 9 * NC];    // [icg 256][tap 9][oc 128]
__device__ float g_WvT[NC * NC];            // [c][o]
__device__ float g_WqT[NC * C8];            // [c][o]
__device__ float g_WkT[NC * C8];            // [c][o]

// ---------------- f32x2 helpers (sm_103a packed fp32 FMA) -----------------
__device__ __forceinline__ ull pack2(float lo, float hi) {
    ull r;
    asm("mov.b64 %0, {%1, %2};" : "=l"(r)
        : "r"(__float_as_uint(lo)), "r"(__float_as_uint(hi)));
    return r;
}
__device__ __forceinline__ void unpack2(ull v, float& lo, float& hi) {
    unsigned ulo, uhi;
    asm("mov.b64 {%0, %1}, %2;" : "=r"(ulo), "=r"(uhi) : "l"(v));
    lo = __uint_as_float(ulo); hi = __uint_as_float(uhi);
}
__device__ __forceinline__ void ffma2(ull& d, ull a, ull b) {
    asm("fma.rn.f32x2 %0, %1, %2, %0;" : "+l"(d) : "l"(a), "l"(b));
}
__device__ __forceinline__ void lds128(ull& a, ull& b, const float* p) {
    unsigned addr = (unsigned)__cvta_generic_to_shared(p);
    asm volatile("ld.shared.v2.b64 {%0, %1}, [%2];"
                 : "=l"(a), "=l"(b) : "r"(addr));
}
__device__ __forceinline__ ull lds64(const float* p) {
    ull r;
    unsigned addr = (unsigned)__cvta_generic_to_shared(p);
    asm volatile("ld.shared.b64 %0, [%1];" : "=l"(r) : "r"(addr));
    return r;
}

// ---------------- K0: weight transposes -----------------------------------
__global__ void k0_transpose(const float* __restrict__ Wq,
                             const float* __restrict__ Wk,
                             const float* __restrict__ Wv,
                             const float* __restrict__ Wf) {
    int t = blockIdx.x * blockDim.x + threadIdx.x;
    int stride = gridDim.x * blockDim.x;
    for (int i = t; i < 256 * 9 * 128; i += stride) {
        int o = i & 127; int tap = (i >> 7) % 9; int ic = i / (128 * 9);
        g_Wt[i] = Wf[(o * 256 + ic) * 9 + tap];
    }
    for (int i = t; i < 128 * 128; i += stride) {
        int o = i & 127; int c = i >> 7;
        g_WvT[i] = Wv[o * 128 + c];
    }
    for (int i = t; i < 128 * 16; i += stride) {
        int o = i & 15; int c = i >> 4;
        g_WqT[i] = Wq[o * 128 + c];
        g_WkT[i] = Wk[o * 128 + c];
    }
}

// ---------------- K1: q/k/v 1x1 projections (f32x2) ------------------------
__global__ __launch_bounds__(128)
void k1_qkv(const float* __restrict__ x,
            const float* __restrict__ xf,
            const float* __restrict__ xb,
            const float* __restrict__ bq,
            const float* __restrict__ bk,
            const float* __restrict__ bv) {
    __shared__ __align__(16) float xs[64 * 128];
    __shared__ __align__(16) float wsf[64 * 32];
    int b  = blockIdx.x >> 5;
    int p0 = (blockIdx.x & 31) * 128;
    int t  = threadIdx.x;

    // ---- keys ----
    {
        ull a[8];
#pragma unroll
        for (int o = 0; o < 8; o++) a[o] = pack2(bk[2 * o], bk[2 * o + 1]);
        for (int cc = 0; cc < 2; cc++) {
            __syncthreads();
            for (int c = 0; c < 64; c++)
                xs[c * 128 + t] = x[(b * 128 + cc * 64 + c) * HWSZ + p0 + t];
            for (int i = t; i < 64 * 16; i += 128)
                wsf[i] = g_WkT[cc * 64 * 16 + i];
            __syncthreads();
#pragma unroll 4
            for (int c = 0; c < 64; c++) {
                float xv = xs[c * 128 + t];
                ull xx = pack2(xv, xv);
                const float* wb = &wsf[c * 16];
                ull w0, w1, w2, w3, w4, w5, w6, w7;
                lds128(w0, w1, wb); lds128(w2, w3, wb + 4);
                lds128(w4, w5, wb + 8); lds128(w6, w7, wb + 12);
                ffma2(a[0], w0, xx); ffma2(a[1], w1, xx);
                ffma2(a[2], w2, xx); ffma2(a[3], w3, xx);
                ffma2(a[4], w4, xx); ffma2(a[5], w5, xx);
                ffma2(a[6], w6, xx); ffma2(a[7], w7, xx);
            }
        }
#pragma unroll
        for (int o = 0; o < 8; o++) {
            float lo, hi; unpack2(a[o], lo, hi);
            g_Kt[b * (C8 * HWSZ) + (2 * o) * HWSZ + p0 + t]     = lo;
            g_Kt[b * (C8 * HWSZ) + (2 * o + 1) * HWSZ + p0 + t] = hi;
        }
    }

    // ---- queries ----
    {
        ull a[8];
#pragma unroll
        for (int o = 0; o < 8; o++) a[o] = pack2(bq[2 * o], bq[2 * o + 1]);
        for (int cc = 0; cc < 2; cc++) {
            __syncthreads();
            for (int c = 0; c < 64; c++)
                xs[c * 128 + t] = xf[(b * 128 + cc * 64 + c) * HWSZ + p0 + t];
            for (int i = t; i < 64 * 16; i += 128)
                wsf[i] = g_WqT[cc * 64 * 16 + i];
            __syncthreads();
#pragma unroll 4
            for (int c = 0; c < 64; c++) {
                float xv = xs[c * 128 + t];
                ull xx = pack2(xv, xv);
                const float* wb = &wsf[c * 16];
                ull w0, w1, w2, w3, w4, w5, w6, w7;
                lds128(w0, w1, wb); lds128(w2, w3, wb + 4);
                lds128(w4, w5, wb + 8); lds128(w6, w7, wb + 12);
                ffma2(a[0], w0, xx); ffma2(a[1], w1, xx);
                ffma2(a[2], w2, xx); ffma2(a[3], w3, xx);
                ffma2(a[4], w4, xx); ffma2(a[5], w5, xx);
                ffma2(a[6], w6, xx); ffma2(a[7], w7, xx);
            }
        }
#pragma unroll
        for (int o = 0; o < 8; o++) {
            float lo, hi; unpack2(a[o], lo, hi);
            g_Qt[b * (C8 * HWSZ) + (2 * o) * HWSZ + p0 + t]     = lo;
            g_Qt[b * (C8 * HWSZ) + (2 * o + 1) * HWSZ + p0 + t] = hi;
        }
    }

    // ---- values ----
    for (int og = 0; og < 4; og++) {
        ull a[16];
#pragma unroll
        for (int o = 0; o < 16; o++)
            a[o] = pack2(bv[og * 32 + 2 * o], bv[og * 32 + 2 * o + 1]);
        for (int cc = 0; cc < 2; cc++) {
            __syncthreads();
            for (int c = 0; c < 64; c++)
                xs[c * 128 + t] = xb[(b * 128 + cc * 64 + c) * HWSZ + p0 + t];
            for (int i = t; i < 64 * 32; i += 128) {
                int c = i >> 5, o = i & 31;
                wsf[i] = g_WvT[(cc * 64 + c) * 128 + og * 32 + o];
            }
            __syncthreads();
#pragma unroll 2
            for (int c = 0; c < 64; c++) {
                float xv = xs[c * 128 + t];
                ull xx = pack2(xv, xv);
                const float* wb = &wsf[c * 32];
#pragma unroll
                for (int o4 = 0; o4 < 8; o4++) {
                    ull w0, w1;
                    lds128(w0, w1, wb + o4 * 4);
                    ffma2(a[o4 * 2 + 0], w0, xx);
                    ffma2(a[o4 * 2 + 1], w1, xx);
                }
            }
        }
#pragma unroll
        for (int o = 0; o < 16; o++) {
            float lo, hi; unpack2(a[o], lo, hi);
            g_V[(b * 128 + og * 32 + 2 * o) * HWSZ + p0 + t]     = lo;
            g_V[(b * 128 + og * 32 + 2 * o + 1) * HWSZ + p0 + t] = hi;
        }
    }
}

// ---------------- K2: attention row max + deferred argmax ------------------
// grid 256 = 4 b x 8 key-blocks(512) x 8 q-partitions(512). Lane owns 2 keys.
// Main loop only tracks the max and the 4-query block index; the exact query
// index is resolved afterward by bitwise-identical recomputation of the
// winning block (first-occurrence preserved: strict >, ascending order).
__device__ __forceinline__ int k2_resolve(const ull* kd, const float* Qs,
                                          int iblk, float m) {
    const float* qbase = Qs + 4 * iblk;
    ull a0 = 0, a1 = 0;
#pragma unroll
    for (int c = 0; c < 16; c++) {
        ull q01, q23;
        lds128(q01, q23, qbase + c * 512);
        ffma2(a0, kd[c], q01);
        ffma2(a1, kd[c], q23);
    }
    float s0, s1, s2, s3;
    unpack2(a0, s0, s1); unpack2(a1, s2, s3);
    int r = 3;
    if (s2 == m) r = 2;
    if (s1 == m) r = 1;
    if (s0 == m) r = 0;
    return 4 * iblk + r;
}

__global__ __launch_bounds__(256, 2)
void k2_attn() {
    __shared__ __align__(16) float Qs[16 * 512];
    int bx = blockIdx.x;
    int qp = bx & 7;
    int kb = (bx >> 3) & 7;
    int b  = bx >> 6;
    int t = threadIdx.x, lane = t & 31, w = t >> 5;

    for (int i = t; i < 8192; i += 256) {
        int c = i >> 9, q = i & 511;
        Qs[i] = g_Qt[b * (C8 * HWSZ) + c * HWSZ + qp * 512 + q];
    }

    int k0r = kb * 512 + w * 64 + lane;
    ull kd0[16], kd1[16];
#pragma unroll
    for (int c = 0; c < 16; c++) {
        float v0 = g_Kt[b * (C8 * HWSZ) + c * HWSZ + k0r];
        float v1 = g_Kt[b * (C8 * HWSZ) + c * HWSZ + k0r + 32];
        kd0[c] = pack2(v0, v0);
        kd1[c] = pack2(v1, v1);
    }
    __syncthreads();

    float m0 = -3.4e38f, m1 = -3.4e38f;
    int ib0 = 0, ib1 = 0;

#pragma unroll 1
    for (int i = 0; i < 128; i++) {
        const float* qbase = &Qs[4 * i];
        ull a0 = 0, a1 = 0, b0 = 0, b1 = 0;
#pragma unroll
        for (int c = 0; c < 16; c++) {
            ull q01, q23;
            lds128(q01, q23, qbase + c * 512);
            ffma2(a0, kd0[c], q01); ffma2(a1, kd0[c], q23);
            ffma2(b0, kd1[c], q01); ffma2(b1, kd1[c], q23);
        }
        float s0, s1, s2, s3;
        unpack2(a0, s0, s1); unpack2(a1, s2, s3);
        float pm = fmaxf(fmaxf(s0, s1), fmaxf(s2, s3));
        if (pm > m0) { m0 = pm; ib0 = i; }
        unpack2(b0, s0, s1); unpack2(b1, s2, s3);
        pm = fmaxf(fmaxf(s0, s1), fmaxf(s2, s3));
        if (pm > m1) { m1 = pm; ib1 = i; }
    }

    int id0 = k2_resolve(kd0, Qs, ib0, m0);
    int id1 = k2_resolve(kd1, Qs, ib1, m1);

    int base = (qp * NB + b) * HWSZ;
    g_m8[base + k0r]      = m0;  g_i8[base + k0r]      = qp * 512 + id0;
    g_m8[base + k0r + 32] = m1;  g_i8[base + k0r + 32] = qp * 512 + id1;
}

// ---------------- K23: merge partitions + gather ----------------------------
// 512 blocks: (b, 32-key chunk). Threads 0-31 merge, then all gather.
__global__ __launch_bounds__(256)
void k23_merge_gather() {
    __shared__ int sidx[32];
    int bx = blockIdx.x;
    int b  = bx >> 7;
    int k0p = (bx & 127) * 32;
    int t = threadIdx.x;

    if (t < 32) {
        int k = k0p + t;
        float m = -3.4e38f; int id = 0;
#pragma unroll
        for (int qp = 0; qp < 8; qp++) {
            float v = g_m8[(qp * NB + b) * HWSZ + k];
            int   i = g_i8[(qp * NB + b) * HWSZ + k];
            if (v > m) { m = v; id = i; }
        }
        g_maxv[b * HWSZ + k] = m;
        sidx[t] = id;
    }
    __syncthreads();

    int p = t & 31;
    int id = sidx[p];
#pragma unroll 4
    for (int c = t >> 5; c < 128; c += 8) {
        int row = (b * 128 + c) * HWSZ;
        g_sel[row + k0p + p] = g_V[row + id];
    }
}

// ---------------- K4: 3x3 conv halves (implicit GEMM, f32x2) ----------------
// grid (16 spatial tiles of 4 rows, 2 oc groups, 4 batches), 256 threads.
// Duplicated-patch smem: x operand is a direct ld.shared.b64 (no pack mov).
__device__ __forceinline__ void conv_half(
    const float* __restrict__ src,   // x (half 0) or g_sel (half 1)
    int half, ull (*acc)[8], int b, int ocg, int h0, int tx, int ty, int t,
    float2* patch2, float* ws) {

#pragma unroll 1
    for (int cc = 0; cc < 16; cc++) {
        __syncthreads();
        for (int i = t; i < 8 * 6 * 68; i += 256) {
            int ic  = i / 408;
            int rem = i - ic * 408;
            int r   = rem / 68;
            int c   = rem - r * 68;
            int gr = h0 - 1 + r, gc = c - 1;
            float v = 0.f;
            if ((unsigned)gr < 64u && (unsigned)gc < 64u)
                v = src[(b * 128 + cc * 8 + ic) * HWSZ + gr * 64 + gc];
            patch2[i] = make_float2(v, v);
        }
        for (int i = t; i < 8 * 9 * 64; i += 256) {
            int ic  = i / 576;
            int rem = i - ic * 576;
            ws[i] = g_Wt[((half * 16 + cc) * 8 + ic) * 1152 +
                         (rem >> 6) * 128 + ocg * 64 + (rem & 63)];
        }
        __syncthreads();

#pragma unroll 1
        for (int ic = 0; ic < 8; ic++) {
            const float* pr = (const float*)(patch2 + ic * 408);
#pragma unroll
            for (int kh = 0; kh < 3; kh++) {
#pragma unroll
                for (int kw = 0; kw < 3; kw++) {
                    const float* wb = &ws[ic * 576 + (kh * 3 + kw) * 64 + ty * 8];
                    ull w0, w1, w2, w3;
                    lds128(w0, w1, wb);
                    lds128(w2, w3, wb + 4);
#pragma unroll
                    for (int j = 0; j < 8; j++) {
                        ull xx = lds64(&pr[((j >> 1) + kh) * 136 +
                                           (tx + kw + ((j & 1) << 5)) * 2]);
                        ffma2(acc[0][j], w0, xx);
                        ffma2(acc[1][j], w1, xx);
                        ffma2(acc[2][j], w2, xx);
                        ffma2(acc[3][j], w3, xx);
                    }
                }
            }
        }
    }
}

__global__ __launch_bounds__(256, 2)
void k4a_conv_x(const float* __restrict__ x) {
    __shared__ __align__(16) float2 patch2[8 * 408];
    __shared__ __align__(16) float  ws[8 * 9 * 64];
    int spt = blockIdx.x, ocg = blockIdx.y, b = blockIdx.z;
    int t = threadIdx.x, tx = t & 31, ty = t >> 5;
    int h0 = spt * 4, p0 = spt * 256;

    ull acc[4][8];
#pragma unroll
    for (int k = 0; k < 4; k++)
#pragma unroll
        for (int j = 0; j < 8; j++) acc[k][j] = 0ull;

    conv_half(x, 0, acc, b, ocg, h0, tx, ty, t, patch2, ws);

    int ocb = ocg * 64 + ty * 8;
#pragma unroll
    for (int j = 0; j < 8; j++) {
        int p = p0 + tx + (j << 5);
#pragma unroll
        for (int k = 0; k < 4; k++) {
            float lo, hi; unpack2(acc[k][j], lo, hi);
            int o0 = (b * 128 + ocb + 2 * k) * HWSZ + p;
            g_part[o0]        = lo;
            g_part[o0 + HWSZ] = hi;
        }
    }
}

__global__ __launch_bounds__(256, 2)
void k4b_conv_sel(const float* __restrict__ x,
                  const float* __restrict__ bf,
                  float* __restrict__ out) {
    __shared__ __align__(16) float2 patch2[8 * 408];
    __shared__ __align__(16) float  ws[8 * 9 * 64];
    int spt = blockIdx.x, ocg = blockIdx.y, b = blockIdx.z;
    int t = threadIdx.x, tx = t & 31, ty = t >> 5;
    int h0 = spt * 4, p0 = spt * 256;

    ull acc[4][8];
#pragma unroll
    for (int k = 0; k < 4; k++)
#pragma unroll
        for (int j = 0; j < 8; j++) acc[k][j] = 0ull;

    conv_half(&g_sel[0], 1, acc, b, ocg, h0, tx, ty, t, patch2, ws);

    // fused epilogue: out = x + (acc + part + bias) * max_value
    int ocb = ocg * 64 + ty * 8;
#pragma unroll
    for (int j = 0; j < 8; j++) {
        int p = p0 + tx + (j << 5);
        float mv = g_maxv[b * HWSZ + p];
#pragma unroll
        for (int k = 0; k < 4; k++) {
            float lo, hi; unpack2(acc[k][j], lo, hi);
            int oc = ocb + 2 * k;
            int o0 = (b * 128 + oc) * HWSZ + p;
            out[o0]        = x[o0]        + (lo + g_part[o0]        + bf[oc])     * mv;
            out[o0 + HWSZ] = x[o0 + HWSZ] + (hi + g_part[o0 + HWSZ] + bf[oc + 1]) * mv;
        }
    }
}

// ---------------- launch -----------------------------------------------------
extern "C" void kernel_launch(void* const* d_in, const int* in_sizes, int n_in,
                              void* d_out, int out_size) {
    const float* x  = (const float*)d_in[0];
    const float* xf = (const float*)d_in[1];
    const float* xb = (const float*)d_in[2];
    const float* Wq = (const float*)d_in[3];
    const float* bq = (const float*)d_in[4];
    const float* Wk = (const float*)d_in[5];
    const float* bk = (const float*)d_in[6];
    const float* Wv = (const float*)d_in[7];
    const float* bv = (const float*)d_in[8];
    const float* Wf = (const float*)d_in[9];
    const float* bf = (const float*)d_in[10];
    float* out = (float*)d_out;

    // order chosen so the 4th launch (which ncu captures) is k4a_conv_x
    k0_transpose<<<256, 256>>>(Wq, Wk, Wv, Wf);
    k1_qkv<<<128, 128>>>(x, xf, xb, bq, bk, bv);
    k2_attn<<<256, 256>>>();
    k4a_conv_x<<<dim3(16, 2, 4), 256>>>(x);
    k23_merge_gather<<<512, 256>>>();
    k4b_conv_sel<<<dim3(16, 2, 4), 256>>>(x, bf, out);
}

// round 7
// speedup vs baseline: 1.3592x; 1.3592x over previous
#include <cuda_runtime.h>

// Problem constants
#define NB   4
#define NC   128
#define C8   16
#define HH   64
#define WW   64
#define HWSZ 4096   // 64*64

typedef unsigned long long ull;

// ---------------- scratch (static device globals; no runtime alloc) -------
__device__ float g_Qt [NB * C8 * HWSZ];     // [b][c8][p]
__device__ float g_Kt [NB * C8 * HWSZ];     // [b][c8][p]
__device__ float g_V  [NB * NC * HWSZ];     // [b][c][p]
__device__ float g_maxv[NB * HWSZ];
__device__ int   g_idx [NB * HWSZ];
__device__ float g_m8 [8 * NB * HWSZ];      // per-q-partition max
__device__ int   g_i8 [8 * NB * HWSZ];      // per-q-partition argmax
__device__ float g_Wt [2 * NC * 9 * NC];    // [icg 256][tap 9][oc 128]

// ---------------- f32x2 helpers (sm_103a packed fp32 FMA) -----------------
__device__ __forceinline__ ull pack2(float lo, float hi) {
    ull r;
    asm("mov.b64 %0, {%1, %2};" : "=l"(r)
        : "r"(__float_as_uint(lo)), "r"(__float_as_uint(hi)));
    return r;
}
__device__ __forceinline__ void unpack2(ull v, float& lo, float& hi) {
    unsigned ulo, uhi;
    asm("mov.b64 {%0, %1}, %2;" : "=r"(ulo), "=r"(uhi) : "l"(v));
    lo = __uint_as_float(ulo); hi = __uint_as_float(uhi);
}
__device__ __forceinline__ void ffma2(ull& d, ull a, ull b) {
    asm("fma.rn.f32x2 %0, %1, %2, %0;" : "+l"(d) : "l"(a), "l"(b));
}
__device__ __forceinline__ void lds128(ull& a, ull& b, const float* p) {
    unsigned addr = (unsigned)__cvta_generic_to_shared(p);
    asm volatile("ld.shared.v2.b64 {%0, %1}, [%2];"
                 : "=l"(a), "=l"(b) : "r"(addr));
}
__device__ __forceinline__ ull lds64(const float* p) {
    ull r;
    unsigned addr = (unsigned)__cvta_generic_to_shared(p);
    asm volatile("ld.shared.b64 %0, [%1];" : "=l"(r) : "r"(addr));
    return r;
}

// ---------------- K1: q/k/v 1x1 projections (f32x2) ------------------------
// Weight transposition happens during smem staging (reads gmem directly).
__global__ __launch_bounds__(128)
void k1_qkv(const float* __restrict__ x,
            const float* __restrict__ xf,
            const float* __restrict__ xb,
            const float* __restrict__ Wq, const float* __restrict__ bq,
            const float* __restrict__ Wk, const float* __restrict__ bk,
            const float* __restrict__ Wv, const float* __restrict__ bv) {
    __shared__ __align__(16) float xs[64 * 128];
    __shared__ __align__(16) float wsf[64 * 32];
    int b  = blockIdx.x >> 5;
    int p0 = (blockIdx.x & 31) * 128;
    int t  = threadIdx.x;

    // ---- keys ----
    {
        ull a[8];
#pragma unroll
        for (int o = 0; o < 8; o++) a[o] = pack2(bk[2 * o], bk[2 * o + 1]);
        for (int cc = 0; cc < 2; cc++) {
            __syncthreads();
            for (int c = 0; c < 64; c++)
                xs[c * 128 + t] = x[(b * 128 + cc * 64 + c) * HWSZ + p0 + t];
            for (int i = t; i < 64 * 16; i += 128) {
                int lc = i >> 4, o = i & 15;
                wsf[i] = Wk[o * 128 + cc * 64 + lc];
            }
            __syncthreads();
#pragma unroll 4
            for (int c = 0; c < 64; c++) {
                float xv = xs[c * 128 + t];
                ull xx = pack2(xv, xv);
                const float* wb = &wsf[c * 16];
                ull w0, w1, w2, w3, w4, w5, w6, w7;
                lds128(w0, w1, wb); lds128(w2, w3, wb + 4);
                lds128(w4, w5, wb + 8); lds128(w6, w7, wb + 12);
                ffma2(a[0], w0, xx); ffma2(a[1], w1, xx);
                ffma2(a[2], w2, xx); ffma2(a[3], w3, xx);
                ffma2(a[4], w4, xx); ffma2(a[5], w5, xx);
                ffma2(a[6], w6, xx); ffma2(a[7], w7, xx);
            }
        }
#pragma unroll
        for (int o = 0; o < 8; o++) {
            float lo, hi; unpack2(a[o], lo, hi);
            g_Kt[b * (C8 * HWSZ) + (2 * o) * HWSZ + p0 + t]     = lo;
            g_Kt[b * (C8 * HWSZ) + (2 * o + 1) * HWSZ + p0 + t] = hi;
        }
    }

    // ---- queries ----
    {
        ull a[8];
#pragma unroll
        for (int o = 0; o < 8; o++) a[o] = pack2(bq[2 * o], bq[2 * o + 1]);
        for (int cc = 0; cc < 2; cc++) {
            __syncthreads();
            for (int c = 0; c < 64; c++)
                xs[c * 128 + t] = xf[(b * 128 + cc * 64 + c) * HWSZ + p0 + t];
            for (int i = t; i < 64 * 16; i += 128) {
                int lc = i >> 4, o = i & 15;
                wsf[i] = Wq[o * 128 + cc * 64 + lc];
            }
            __syncthreads();
#pragma unroll 4
            for (int c = 0; c < 64; c++) {
                float xv = xs[c * 128 + t];
                ull xx = pack2(xv, xv);
                const float* wb = &wsf[c * 16];
                ull w0, w1, w2, w3, w4, w5, w6, w7;
                lds128(w0, w1, wb); lds128(w2, w3, wb + 4);
                lds128(w4, w5, wb + 8); lds128(w6, w7, wb + 12);
                ffma2(a[0], w0, xx); ffma2(a[1], w1, xx);
                ffma2(a[2], w2, xx); ffma2(a[3], w3, xx);
                ffma2(a[4], w4, xx); ffma2(a[5], w5, xx);
                ffma2(a[6], w6, xx); ffma2(a[7], w7, xx);
            }
        }
#pragma unroll
        for (int o = 0; o < 8; o++) {
            float lo, hi; unpack2(a[o], lo, hi);
            g_Qt[b * (C8 * HWSZ) + (2 * o) * HWSZ + p0 + t]     = lo;
            g_Qt[b * (C8 * HWSZ) + (2 * o + 1) * HWSZ + p0 + t] = hi;
        }
    }

    // ---- values ----
    for (int og = 0; og < 4; og++) {
        ull a[16];
#pragma unroll
        for (int o = 0; o < 16; o++)
            a[o] = pack2(bv[og * 32 + 2 * o], bv[og * 32 + 2 * o + 1]);
        for (int cc = 0; cc < 2; cc++) {
            __syncthreads();
            for (int c = 0; c < 64; c++)
                xs[c * 128 + t] = xb[(b * 128 + cc * 64 + c) * HWSZ + p0 + t];
            for (int i = t; i < 64 * 32; i += 128) {
                int lc = i >> 5, o = i & 31;
                wsf[i] = Wv[(og * 32 + o) * 128 + cc * 64 + lc];
            }
            __syncthreads();
#pragma unroll 2
            for (int c = 0; c < 64; c++) {
                float xv = xs[c * 128 + t];
                ull xx = pack2(xv, xv);
                const float* wb = &wsf[c * 32];
#pragma unroll
                for (int o4 = 0; o4 < 8; o4++) {
                    ull w0, w1;
                    lds128(w0, w1, wb + o4 * 4);
                    ffma2(a[o4 * 2 + 0], w0, xx);
                    ffma2(a[o4 * 2 + 1], w1, xx);
                }
            }
        }
#pragma unroll
        for (int o = 0; o < 16; o++) {
            float lo, hi; unpack2(a[o], lo, hi);
            g_V[(b * 128 + og * 32 + 2 * o) * HWSZ + p0 + t]     = lo;
            g_V[(b * 128 + og * 32 + 2 * o + 1) * HWSZ + p0 + t] = hi;
        }
    }
}

// ---------------- K2: attention row max + deferred argmax ------------------
__device__ __forceinline__ int k2_resolve(const ull* kd, const float* Qs,
                                          int iblk, float m) {
    const float* qbase = Qs + 4 * iblk;
    ull a0 = 0, a1 = 0;
#pragma unroll
    for (int c = 0; c < 16; c++) {
        ull q01, q23;
        lds128(q01, q23, qbase + c * 512);
        ffma2(a0, kd[c], q01);
        ffma2(a1, kd[c], q23);
    }
    float s0, s1, s2, s3;
    unpack2(a0, s0, s1); unpack2(a1, s2, s3);
    int r = 3;
    if (s2 == m) r = 2;
    if (s1 == m) r = 1;
    if (s0 == m) r = 0;
    return 4 * iblk + r;
}

__global__ __launch_bounds__(256, 2)
void k2_attn() {
    __shared__ __align__(16) float Qs[16 * 512];
    int bx = blockIdx.x;
    int qp = bx & 7;
    int kb = (bx >> 3) & 7;
    int b  = bx >> 6;
    int t = threadIdx.x, lane = t & 31, w = t >> 5;

    for (int i = t; i < 8192; i += 256) {
        int c = i >> 9, q = i & 511;
        Qs[i] = g_Qt[b * (C8 * HWSZ) + c * HWSZ + qp * 512 + q];
    }

    int k0r = kb * 512 + w * 64 + lane;
    ull kd0[16], kd1[16];
#pragma unroll
    for (int c = 0; c < 16; c++) {
        float v0 = g_Kt[b * (C8 * HWSZ) + c * HWSZ + k0r];
        float v1 = g_Kt[b * (C8 * HWSZ) + c * HWSZ + k0r + 32];
        kd0[c] = pack2(v0, v0);
        kd1[c] = pack2(v1, v1);
    }
    __syncthreads();

    float m0 = -3.4e38f, m1 = -3.4e38f;
    int ib0 = 0, ib1 = 0;

#pragma unroll 1
    for (int i = 0; i < 128; i++) {
        const float* qbase = &Qs[4 * i];
        ull a0 = 0, a1 = 0, b0 = 0, b1 = 0;
#pragma unroll
        for (int c = 0; c < 16; c++) {
            ull q01, q23;
            lds128(q01, q23, qbase + c * 512);
            ffma2(a0, kd0[c], q01); ffma2(a1, kd0[c], q23);
            ffma2(b0, kd1[c], q01); ffma2(b1, kd1[c], q23);
        }
        float s0, s1, s2, s3;
        unpack2(a0, s0, s1); unpack2(a1, s2, s3);
        float pm = fmaxf(fmaxf(s0, s1), fmaxf(s2, s3));
        if (pm > m0) { m0 = pm; ib0 = i; }
        unpack2(b0, s0, s1); unpack2(b1, s2, s3);
        pm = fmaxf(fmaxf(s0, s1), fmaxf(s2, s3));
        if (pm > m1) { m1 = pm; ib1 = i; }
    }

    int id0 = k2_resolve(kd0, Qs, ib0, m0);
    int id1 = k2_resolve(kd1, Qs, ib1, m1);

    int base = (qp * NB + b) * HWSZ;
    g_m8[base + k0r]      = m0;  g_i8[base + k0r]      = qp * 512 + id0;
    g_m8[base + k0r + 32] = m1;  g_i8[base + k0r + 32] = qp * 512 + id1;
}

// ---------------- K3: merge partitions + conv-weight transpose --------------
__global__ __launch_bounds__(256)
void k3_prep(const float* __restrict__ Wf) {
    int gid = blockIdx.x * 256 + threadIdx.x;   // grid 128 -> 32768 threads

    if (gid < NB * HWSZ) {
        int b = gid >> 12, k = gid & (HWSZ - 1);
        float m = -3.4e38f; int id = 0;
#pragma unroll
        for (int qp = 0; qp < 8; qp++) {
            float v = g_m8[(qp * NB + b) * HWSZ + k];
            int   i = g_i8[(qp * NB + b) * HWSZ + k];
            if (v > m) { m = v; id = i; }
        }
        g_maxv[gid] = m;
        g_idx [gid] = id;
    }
    // Wf [o=128][ic=256][3][3] -> g_Wt [ic][tap][o]
    for (int i = gid; i < 256 * 9 * 128; i += 32768) {
        int o = i & 127; int tap = (i >> 7) % 9; int ic = i / (128 * 9);
        g_Wt[i] = Wf[(o * 256 + ic) * 9 + tap];
    }
}

// ---------------- K4: fused 3x3 conv (pixel-pair f32x2) + epilogue ----------
// grid (32 spatial tiles of 2 rows, 2 ocg of 64, 4 batches), 256 threads,
// 2 CTAs/SM. Thread = 8 oc x 2 pixel-pairs (2 rows x cols 2tx,2tx+1).
// x operand: aligned ld.shared.b64 pixel pair (kw=1 composed by one mov).
// w operand: duplicated pair in smem, warp-uniform broadcast load.
__global__ __launch_bounds__(256, 2)
void k4_conv(const float* __restrict__ x,
             const float* __restrict__ bf,
             float* __restrict__ out) {
    __shared__ __align__(16) ull   wdup[8 * 9 * 64];   // 36864 B
    __shared__ __align__(16) float patch[8 * 4 * 68];  // 8704 B
    __shared__ int sidx[4 * 68];                       // 1088 B
    int spt = blockIdx.x;          // 0..31 -> rows h0=2*spt
    int ocg = blockIdx.y;          // 0..1
    int b   = blockIdx.z;          // 0..3
    int t = threadIdx.x, tx = t & 31, ty = t >> 5;
    int h0 = spt * 2;

    // stage gather indices for this tile's patch rows (once)
    for (int i = t; i < 272; i += 256) {
        int r = i / 68, c = i - r * 68;
        int gr = h0 - 1 + r, gc = c - 1;
        sidx[i] = ((unsigned)gr < 64u && (unsigned)gc < 64u)
                      ? g_idx[b * HWSZ + gr * 64 + gc] : 0;
    }

    ull acc[8][2];
#pragma unroll
    for (int o = 0; o < 8; o++) { acc[o][0] = 0ull; acc[o][1] = 0ull; }

#pragma unroll 1
    for (int chunk = 0; chunk < 32; chunk++) {
        __syncthreads();
        // ---- stage patch [8 ic][4 rows][68 cols] (zero halo) ----
        for (int i = t; i < 2176; i += 256) {
            int ic  = i / 272;
            int rem = i - ic * 272;
            int r   = rem / 68;
            int c   = rem - r * 68;
            int gr = h0 - 1 + r, gc = c - 1;
            float v = 0.f;
            if ((unsigned)gr < 64u && (unsigned)gc < 64u) {
                int icg = chunk * 8 + ic;
                v = (icg < 128)
                        ? x[(b * 128 + icg) * HWSZ + gr * 64 + gc]
                        : g_V[(b * 128 + icg - 128) * HWSZ + sidx[rem]];
            }
            patch[i] = v;
        }
        // ---- stage duplicated weights [8 ic][9 tap][64 oc] ----
        for (int i = t; i < 4608; i += 256) {
            int ic  = i / 576;
            int rem = i - ic * 576;
            float w = g_Wt[(chunk * 8 + ic) * 1152 +
                           (rem >> 6) * 128 + ocg * 64 + (rem & 63)];
            wdup[i] = pack2(w, w);
        }
        __syncthreads();

#pragma unroll 1
        for (int ic = 0; ic < 8; ic++) {
            const float* pr = &patch[ic * 272];
            ull A[4], B[4], Cc[4];
#pragma unroll
            for (int r = 0; r < 4; r++) {
                A[r] = lds64(&pr[r * 68 + 2 * tx]);
                B[r] = lds64(&pr[r * 68 + 2 * tx + 2]);
                float al, ah, bl, bh;
                unpack2(A[r], al, ah); unpack2(B[r], bl, bh);
                Cc[r] = pack2(ah, bl);
            }
#pragma unroll
            for (int kh = 0; kh < 3; kh++) {
#pragma unroll
                for (int kw = 0; kw < 3; kw++) {
                    const ull* wb = &wdup[ic * 576 + (kh * 3 + kw) * 64 + ty * 8];
                    ull w0 = wb[0], w1 = wb[1], w2 = wb[2], w3 = wb[3];
                    ull w4 = wb[4], w5 = wb[5], w6 = wb[6], w7 = wb[7];
#pragma unroll
                    for (int r = 0; r < 2; r++) {
                        ull xp = (kw == 0) ? A[r + kh]
                               : (kw == 1) ? Cc[r + kh] : B[r + kh];
                        ffma2(acc[0][r], w0, xp); ffma2(acc[1][r], w1, xp);
                        ffma2(acc[2][r], w2, xp); ffma2(acc[3][r], w3, xp);
                        ffma2(acc[4][r], w4, xp); ffma2(acc[5][r], w5, xp);
                        ffma2(acc[6][r], w6, xp); ffma2(acc[7][r], w7, xp);
                    }
                }
            }
        }
    }

    // ---- fused epilogue: out = x + (acc + bias) * max_value ----
    int ocb = ocg * 64 + ty * 8;
#pragma unroll
    for (int r = 0; r < 2; r++) {
        int p = (h0 + r) * 64 + 2 * tx;
        float m0 = g_maxv[b * HWSZ + p];
        float m1 = g_maxv[b * HWSZ + p + 1];
#pragma unroll
        for (int o = 0; o < 8; o++) {
            float lo, hi; unpack2(acc[o][r], lo, hi);
            int oc = ocb + o;
            float bb = bf[oc];
            int o0 = (b * 128 + oc) * HWSZ + p;
            out[o0]     = x[o0]     + (lo + bb) * m0;
            out[o0 + 1] = x[o0 + 1] + (hi + bb) * m1;
        }
    }
}

// ---------------- launch -----------------------------------------------------
extern "C" void kernel_launch(void* const* d_in, const int* in_sizes, int n_in,
                              void* d_out, int out_size) {
    const float* x  = (const float*)d_in[0];
    const float* xf = (const float*)d_in[1];
    const float* xb = (const float*)d_in[2];
    const float* Wq = (const float*)d_in[3];
    const float* bq = (const float*)d_in[4];
    const float* Wk = (const float*)d_in[5];
    const float* bk = (const float*)d_in[6];
    const float* Wv = (const float*)d_in[7];
    const float* bv = (const float*)d_in[8];
    const float* Wf = (const float*)d_in[9];
    const float* bf = (const float*)d_in[10];
    float* out = (float*)d_out;

    // 4 launches: ncu's capture (skip 5 under graph warmup) lands on k4_conv
    k1_qkv<<<128, 128>>>(x, xf, xb, Wq, bq, Wk, bk, Wv, bv);
    k2_attn<<<256, 256>>>();
    k3_prep<<<128, 256>>>(Wf);
    k4_conv<<<dim3(32, 2, 4), 256>>>(x, bf, out);
}

// round 9
// speedup vs baseline: 1.5789x; 1.1616x over previous
#include <cuda_runtime.h>

// Problem constants
#define NB   4
#define NC   128
#define C8   16
#define HH   64
#define WW   64
#define HWSZ 4096   // 64*64

typedef unsigned long long ull;

// ---------------- scratch (static device globals; no runtime alloc) -------
__device__ float g_Qt [NB * C8 * HWSZ];     // [b][c8][p]
__device__ float g_Kt [NB * C8 * HWSZ];     // [b][c8][p]
__device__ float g_V  [NB * NC * HWSZ];     // [b][c][p]
__device__ float g_maxv[NB * HWSZ];
__device__ int   g_idx [NB * HWSZ];
__device__ float g_m8 [8 * NB * HWSZ];      // per-q-partition max
__device__ int   g_i8 [8 * NB * HWSZ];      // per-q-partition argmax
__device__ float g_Wt [2 * NC * 9 * NC];    // [icg 256][tap 9][oc 128]

// ---------------- f32x2 helpers (sm_103a packed fp32 FMA) -----------------
__device__ __forceinline__ ull pack2(float lo, float hi) {
    ull r;
    asm("mov.b64 %0, {%1, %2};" : "=l"(r)
        : "r"(__float_as_uint(lo)), "r"(__float_as_uint(hi)));
    return r;
}
__device__ __forceinline__ void unpack2(ull v, float& lo, float& hi) {
    unsigned ulo, uhi;
    asm("mov.b64 {%0, %1}, %2;" : "=r"(ulo), "=r"(uhi) : "l"(v));
    lo = __uint_as_float(ulo); hi = __uint_as_float(uhi);
}
__device__ __forceinline__ void ffma2(ull& d, ull a, ull b) {
    asm("fma.rn.f32x2 %0, %1, %2, %0;" : "+l"(d) : "l"(a), "l"(b));
}
__device__ __forceinline__ void lds128(ull& a, ull& b, const float* p) {
    unsigned addr = (unsigned)__cvta_generic_to_shared(p);
    asm volatile("ld.shared.v2.b64 {%0, %1}, [%2];"
                 : "=l"(a), "=l"(b) : "r"(addr));
}

// ---------------- K1: q/k/v 1x1 projections (f32x2) ------------------------
__global__ __launch_bounds__(128)
void k1_qkv(const float* __restrict__ x,
            const float* __restrict__ xf,
            const float* __restrict__ xb,
            const float* __restrict__ Wq, const float* __restrict__ bq,
            const float* __restrict__ Wk, const float* __restrict__ bk,
            const float* __restrict__ Wv, const float* __restrict__ bv) {
    __shared__ __align__(16) float xs[64 * 128];
    __shared__ __align__(16) float wsf[64 * 32];
    int b  = blockIdx.x >> 5;
    int p0 = (blockIdx.x & 31) * 128;
    int t  = threadIdx.x;

    // ---- keys ----
    {
        ull a[8];
#pragma unroll
        for (int o = 0; o < 8; o++) a[o] = pack2(bk[2 * o], bk[2 * o + 1]);
        for (int cc = 0; cc < 2; cc++) {
            __syncthreads();
            for (int c = 0; c < 64; c++)
                xs[c * 128 + t] = x[(b * 128 + cc * 64 + c) * HWSZ + p0 + t];
            for (int i = t; i < 64 * 16; i += 128) {
                int lc = i >> 4, o = i & 15;
                wsf[i] = Wk[o * 128 + cc * 64 + lc];
            }
            __syncthreads();
#pragma unroll 4
            for (int c = 0; c < 64; c++) {
                float xv = xs[c * 128 + t];
                ull xx = pack2(xv, xv);
                const float* wb = &wsf[c * 16];
                ull w0, w1, w2, w3, w4, w5, w6, w7;
                lds128(w0, w1, wb); lds128(w2, w3, wb + 4);
                lds128(w4, w5, wb + 8); lds128(w6, w7, wb + 12);
                ffma2(a[0], w0, xx); ffma2(a[1], w1, xx);
                ffma2(a[2], w2, xx); ffma2(a[3], w3, xx);
                ffma2(a[4], w4, xx); ffma2(a[5], w5, xx);
                ffma2(a[6], w6, xx); ffma2(a[7], w7, xx);
            }
        }
#pragma unroll
        for (int o = 0; o < 8; o++) {
            float lo, hi; unpack2(a[o], lo, hi);
            g_Kt[b * (C8 * HWSZ) + (2 * o) * HWSZ + p0 + t]     = lo;
            g_Kt[b * (C8 * HWSZ) + (2 * o + 1) * HWSZ + p0 + t] = hi;
        }
    }

    // ---- queries ----
    {
        ull a[8];
#pragma unroll
        for (int o = 0; o < 8; o++) a[o] = pack2(bq[2 * o], bq[2 * o + 1]);
        for (int cc = 0; cc < 2; cc++) {
            __syncthreads();
            for (int c = 0; c < 64; c++)
                xs[c * 128 + t] = xf[(b * 128 + cc * 64 + c) * HWSZ + p0 + t];
            for (int i = t; i < 64 * 16; i += 128) {
                int lc = i >> 4, o = i & 15;
                wsf[i] = Wq[o * 128 + cc * 64 + lc];
            }
            __syncthreads();
#pragma unroll 4
            for (int c = 0; c < 64; c++) {
                float xv = xs[c * 128 + t];
                ull xx = pack2(xv, xv);
                const float* wb = &wsf[c * 16];
                ull w0, w1, w2, w3, w4, w5, w6, w7;
                lds128(w0, w1, wb); lds128(w2, w3, wb + 4);
                lds128(w4, w5, wb + 8); lds128(w6, w7, wb + 12);
                ffma2(a[0], w0, xx); ffma2(a[1], w1, xx);
                ffma2(a[2], w2, xx); ffma2(a[3], w3, xx);
                ffma2(a[4], w4, xx); ffma2(a[5], w5, xx);
                ffma2(a[6], w6, xx); ffma2(a[7], w7, xx);
            }
        }
#pragma unroll
        for (int o = 0; o < 8; o++) {
            float lo, hi; unpack2(a[o], lo, hi);
            g_Qt[b * (C8 * HWSZ) + (2 * o) * HWSZ + p0 + t]     = lo;
            g_Qt[b * (C8 * HWSZ) + (2 * o + 1) * HWSZ + p0 + t] = hi;
        }
    }

    // ---- values ----
    for (int og = 0; og < 4; og++) {
        ull a[16];
#pragma unroll
        for (int o = 0; o < 16; o++)
            a[o] = pack2(bv[og * 32 + 2 * o], bv[og * 32 + 2 * o + 1]);
        for (int cc = 0; cc < 2; cc++) {
            __syncthreads();
            for (int c = 0; c < 64; c++)
                xs[c * 128 + t] = xb[(b * 128 + cc * 64 + c) * HWSZ + p0 + t];
            for (int i = t; i < 64 * 32; i += 128) {
                int lc = i >> 5, o = i & 31;
                wsf[i] = Wv[(og * 32 + o) * 128 + cc * 64 + lc];
            }
            __syncthreads();
#pragma unroll 2
            for (int c = 0; c < 64; c++) {
                float xv = xs[c * 128 + t];
                ull xx = pack2(xv, xv);
                const float* wb = &wsf[c * 32];
#pragma unroll
                for (int o4 = 0; o4 < 8; o4++) {
                    ull w0, w1;
                    lds128(w0, w1, wb + o4 * 4);
                    ffma2(a[o4 * 2 + 0], w0, xx);
                    ffma2(a[o4 * 2 + 1], w1, xx);
                }
            }
        }
#pragma unroll
        for (int o = 0; o < 16; o++) {
            float lo, hi; unpack2(a[o], lo, hi);
            g_V[(b * 128 + og * 32 + 2 * o) * HWSZ + p0 + t]     = lo;
            g_V[(b * 128 + og * 32 + 2 * o + 1) * HWSZ + p0 + t] = hi;
        }
    }
}

// ---------------- K2: attention row max + deferred argmax ------------------
__device__ __forceinline__ int k2_resolve(const ull* kd, const float* Qs,
                                          int iblk, float m) {
    const float* qbase = Qs + 4 * iblk;
    ull a0 = 0, a1 = 0;
#pragma unroll
    for (int c = 0; c < 16; c++) {
        ull q01, q23;
        lds128(q01, q23, qbase + c * 512);
        ffma2(a0, kd[c], q01);
        ffma2(a1, kd[c], q23);
    }
    float s0, s1, s2, s3;
    unpack2(a0, s0, s1); unpack2(a1, s2, s3);
    int r = 3;
    if (s2 == m) r = 2;
    if (s1 == m) r = 1;
    if (s0 == m) r = 0;
    return 4 * iblk + r;
}

__global__ __launch_bounds__(256, 2)
void k2_attn() {
    __shared__ __align__(16) float Qs[16 * 512];
    int bx = blockIdx.x;
    int qp = bx & 7;
    int kb = (bx >> 3) & 7;
    int b  = bx >> 6;
    int t = threadIdx.x, lane = t & 31, w = t >> 5;

    for (int i = t; i < 8192; i += 256) {
        int c = i >> 9, q = i & 511;
        Qs[i] = g_Qt[b * (C8 * HWSZ) + c * HWSZ + qp * 512 + q];
    }

    int k0r = kb * 512 + w * 64 + lane;
    ull kd0[16], kd1[16];
#pragma unroll
    for (int c = 0; c < 16; c++) {
        float v0 = g_Kt[b * (C8 * HWSZ) + c * HWSZ + k0r];
        float v1 = g_Kt[b * (C8 * HWSZ) + c * HWSZ + k0r + 32];
        kd0[c] = pack2(v0, v0);
        kd1[c] = pack2(v1, v1);
    }
    __syncthreads();

    float m0 = -3.4e38f, m1 = -3.4e38f;
    int ib0 = 0, ib1 = 0;

#pragma unroll 1
    for (int i = 0; i < 128; i++) {
        const float* qbase = &Qs[4 * i];
        ull a0 = 0, a1 = 0, b0 = 0, b1 = 0;
#pragma unroll
        for (int c = 0; c < 16; c++) {
            ull q01, q23;
            lds128(q01, q23, qbase + c * 512);
            ffma2(a0, kd0[c], q01); ffma2(a1, kd0[c], q23);
            ffma2(b0, kd1[c], q01); ffma2(b1, kd1[c], q23);
        }
        float s0, s1, s2, s3;
        unpack2(a0, s0, s1); unpack2(a1, s2, s3);
        float pm = fmaxf(fmaxf(s0, s1), fmaxf(s2, s3));
        if (pm > m0) { m0 = pm; ib0 = i; }
        unpack2(b0, s0, s1); unpack2(b1, s2, s3);
        pm = fmaxf(fmaxf(s0, s1), fmaxf(s2, s3));
        if (pm > m1) { m1 = pm; ib1 = i; }
    }

    int id0 = k2_resolve(kd0, Qs, ib0, m0);
    int id1 = k2_resolve(kd1, Qs, ib1, m1);

    int base = (qp * NB + b) * HWSZ;
    g_m8[base + k0r]      = m0;  g_i8[base + k0r]      = qp * 512 + id0;
    g_m8[base + k0r + 32] = m1;  g_i8[base + k0r + 32] = qp * 512 + id1;
}

// ---------------- K3: merge partitions + conv-weight transpose --------------
__global__ __launch_bounds__(256)
void k3_prep(const float* __restrict__ Wf) {
    int gid = blockIdx.x * 256 + threadIdx.x;   // grid 128 -> 32768 threads

    if (gid < NB * HWSZ) {
        int b = gid >> 12, k = gid & (HWSZ - 1);
        float m = -3.4e38f; int id = 0;
#pragma unroll
        for (int qp = 0; qp < 8; qp++) {
            float v = g_m8[(qp * NB + b) * HWSZ + k];
            int   i = g_i8[(qp * NB + b) * HWSZ + k];
            if (v > m) { m = v; id = i; }
        }
        g_maxv[gid] = m;
        g_idx [gid] = id;
    }
    // Wf [o=128][ic=256][3][3] -> g_Wt [ic][tap][o]
    for (int i = gid; i < 256 * 9 * 128; i += 32768) {
        int o = i & 127; int tap = (i >> 7) % 9; int ic = i / (128 * 9);
        g_Wt[i] = Wf[(o * 256 + ic) * 9 + tap];
    }
}

// ---------------- K4: fused 3x3 conv (oc-pair f32x2) + epilogue -------------
// grid (32 spatial tiles of 2 rows, 2 ocg of 64, 4 batches), 256 threads,
// 2 CTAs/SM. Thread = 8 oc (4 f32x2 oc-pairs) x 4 pixels.
// Inner loop: weights via 2x broadcast lds128, x via stride-1 scalar LDS
// + one dup-pack per 4 FFMA2. ic chunks of 16 (32 barriers total).
__global__ __launch_bounds__(256, 2)
void k4_conv(const float* __restrict__ x,
             const float* __restrict__ bf,
             float* __restrict__ out) {
    __shared__ __align__(16) float patch[16 * 4 * 68];  // 17408 B
    __shared__ __align__(16) float ws[16 * 9 * 64];     // 36864 B
    __shared__ int sidx[4 * 68];                        // 1088 B
    int spt = blockIdx.x;          // 0..31 -> rows h0=2*spt
    int ocg = blockIdx.y;          // 0..1
    int b   = blockIdx.z;          // 0..3
    int t = threadIdx.x, tx = t & 31, ty = t >> 5;
    int h0 = spt * 2;

    // stage gather indices for this tile's patch rows (once)
    for (int i = t; i < 272; i += 256) {
        int r = i / 68, c = i - r * 68;
        int gr = h0 - 1 + r, gc = c - 1;
        sidx[i] = ((unsigned)gr < 64u && (unsigned)gc < 64u)
                      ? g_idx[b * HWSZ + gr * 64 + gc] : 0;
    }

    ull acc[4][4];
#pragma unroll
    for (int k = 0; k < 4; k++)
#pragma unroll
        for (int j = 0; j < 4; j++) acc[k][j] = 0ull;

#pragma unroll 1
    for (int chunk = 0; chunk < 16; chunk++) {
        __syncthreads();
        // ---- stage patch [16 ic][4 rows][68 cols] (zero halo) ----
        for (int i = t; i < 4352; i += 256) {
            int ic  = i / 272;
            int rem = i - ic * 272;
            int r   = rem / 68;
            int c   = rem - r * 68;
            int gr = h0 - 1 + r, gc = c - 1;
            float v = 0.f;
            if ((unsigned)gr < 64u && (unsigned)gc < 64u) {
                int icg = chunk * 16 + ic;
                v = (icg < 128)
                        ? x[(b * 128 + icg) * HWSZ + gr * 64 + gc]
                        : g_V[(b * 128 + icg - 128) * HWSZ + sidx[rem]];
            }
            patch[i] = v;
        }
        // ---- stage weights [16 ic][9 tap][64 oc] ----
        for (int i = t; i < 9216; i += 256) {
            int ic  = i / 576;
            int rem = i - ic * 576;
            ws[i] = g_Wt[(chunk * 16 + ic) * 1152 +
                         (rem >> 6) * 128 + ocg * 64 + (rem & 63)];
        }
        __syncthreads();

#pragma unroll 1
        for (int ic = 0; ic < 16; ic++) {
            const float* pr = &patch[ic * 272];
#pragma unroll
            for (int kh = 0; kh < 3; kh++) {
#pragma unroll
                for (int kw = 0; kw < 3; kw++) {
                    const float* wb = &ws[ic * 576 + (kh * 3 + kw) * 64 + ty * 8];
                    ull w0, w1, w2, w3;
                    lds128(w0, w1, wb);
                    lds128(w2, w3, wb + 4);
                    int cb = tx + kw;
#pragma unroll
                    for (int j = 0; j < 4; j++) {
                        float xv = pr[((j >> 1) + kh) * 68 + cb + ((j & 1) << 5)];
                        ull xx = pack2(xv, xv);
                        ffma2(acc[0][j], w0, xx);
                        ffma2(acc[1][j], w1, xx);
                        ffma2(acc[2][j], w2, xx);
                        ffma2(acc[3][j], w3, xx);
                    }
                }
            }
        }
    }

    // ---- fused epilogue: out = x + (acc + bias) * max_value ----
    int ocb = ocg * 64 + ty * 8;
#pragma unroll
    for (int j = 0; j < 4; j++) {
        int p = (h0 + (j >> 1)) * 64 + tx + ((j & 1) << 5);
        float mv = g_maxv[b * HWSZ + p];
#pragma unroll
        for (int k = 0; k < 4; k++) {
            float lo, hi; unpack2(acc[k][j], lo, hi);
            int oc = ocb + 2 * k;
            int o0 = (b * 128 + oc) * HWSZ + p;
            out[o0]        = x[o0]        + (lo + bf[oc])     * mv;
            out[o0 + HWSZ] = x[o0 + HWSZ] + (hi + bf[oc + 1]) * mv;
        }
    }
}

// ---------------- launch -----------------------------------------------------
extern "C" void kernel_launch(void* const* d_in, const int* in_sizes, int n_in,
                              void* d_out, int out_size) {
    const float* x  = (const float*)d_in[0];
    const float* xf = (const float*)d_in[1];
    const float* xb = (const float*)d_in[2];
    const float* Wq = (const float*)d_in[3];
    const float* bq = (const float*)d_in[4];
    const float* Wk = (const float*)d_in[5];
    const float* bk = (const float*)d_in[6];
    const float* Wv = (const float*)d_in[7];
    const float* bv = (const float*)d_in[8];
    const float* Wf = (const float*)d_in[9];
    const float* bf = (const float*)d_in[10];
    float* out = (float*)d_out;

    // 4 launches: ncu capture lands on k4_conv
    k1_qkv<<<128, 128>>>(x, xf, xb, Wq, bq, Wk, bk, Wv, bv);
    k2_attn<<<256, 256>>>();
    k3_prep<<<128, 256>>>(Wf);
    k4_conv<<<dim3(32, 2, 4), 256>>>(x, bf, out);
}